// round 5
// baseline (speedup 1.0000x reference)
#include <cuda_runtime.h>
#include <cuda_bf16.h>
#include <math.h>

#define B_   256
#define IN_  64
#define HID_ 128
#define OUT_ 64
#define T_   1000
#define CH_  10
#define CL_  100

// ---------------- device scratch (static, allocation-free) ----------------
__device__ float g_xeff[(size_t)B_ * IN_ * T_];   // (b, i, t) effective x
__device__ float g_gxT [(size_t)B_ * IN_ * T_];   // (b, n, t) gamma_x
// per (b,t): [0:128)=gamma_h  [128:256)=A_z  [256:384)=A_r  [384:512)=A_h
__device__ float g_act [(size_t)B_ * T_ * 512];
__device__ float g_wzrh[128 * 384];               // packed [x;m] -> [z|r|h]
__device__ float g_bzrh[384];
__device__ float g_lastx[B_ * IN_ * CH_];
__device__ float g_hasx [B_ * IN_ * CH_];

__device__ __forceinline__ float sigf(float x) { return 1.0f / (1.0f + __expf(-x)); }
__device__ __forceinline__ float tanhfast(float x) {
    float e = __expf(-2.0f * fabsf(x));
    float r = (1.0f - e) / (1.0f + e);
    return copysignf(r, x);
}
// packed f32x2 FMA (sm_10x)
__device__ __forceinline__ unsigned long long ffma2(unsigned long long a,
                                                    unsigned long long b,
                                                    unsigned long long c) {
    unsigned long long d;
    asm("fma.rn.f32x2 %0, %1, %2, %3;" : "=l"(d) : "l"(a), "l"(b), "l"(c));
    return d;
}
__device__ __forceinline__ unsigned long long pack2(float w) {
    unsigned long long d;
    asm("mov.b64 %0, {%1, %1};" : "=l"(d) : "f"(w));
    return d;
}
__device__ __forceinline__ unsigned long long packf2(float a, float b) {
    unsigned long long d;
    asm("mov.b64 %0, {%1, %2};" : "=l"(d) : "f"(a), "f"(b));
    return d;
}
__device__ __forceinline__ float2 up2(unsigned long long u) {
    return make_float2(__uint_as_float((unsigned)u),
                       __uint_as_float((unsigned)(u >> 32)));
}
__device__ __forceinline__ float hsum2(unsigned long long u) {
    float2 c = up2(u);
    return c.x + c.y;
}

// ---------------- pack combined [x;m] weights -----------------------------
__global__ void pack_kernel(const float* __restrict__ Wxz, const float* __restrict__ Wmz,
                            const float* __restrict__ bmz,
                            const float* __restrict__ Wxr, const float* __restrict__ Wmr,
                            const float* __restrict__ Wxh, const float* __restrict__ Wmh,
                            const float* __restrict__ bmh) {
    for (int idx = threadIdx.x; idx < 128 * 384; idx += blockDim.x) {
        int k = idx / 384, n = idx % 384;
        int mat = n >> 7, j = n & 127;
        const float* Wx = (mat == 0) ? Wxz : ((mat == 1) ? Wxr : Wxh);
        const float* Wm = (mat == 0) ? Wmz : ((mat == 1) ? Wmr : Wmh);
        g_wzrh[idx] = (k < 64) ? Wx[k * 128 + j] : Wm[(k - 64) * 128 + j];
    }
    for (int n = threadIdx.x; n < 384; n += blockDim.x) {
        int mat = n >> 7, j = n & 127;
        g_bzrh[n] = (mat == 0) ? bmz[j] : ((mat == 2) ? bmh[j] : 0.0f);
    }
}

// ---------------- GEMM over feature-major A (f32x2, 128x128 tile) ----------
__global__ __launch_bounds__(256, 2)
void gemmT_kernel(const float* __restrict__ Ain,
                  const float* __restrict__ W_in, int ldw, int Ncols,
                  const float* __restrict__ bias_in,
                  int K, int actMode, int outMode, int outOff, int srcMode) {
    __shared__ __align__(16) float As[16 * 132];
    __shared__ __align__(16) float Bs[16 * 128];
    const float* Wp = srcMode ? g_wzrh : W_in;
    const float* bp = srcMode ? g_bzrh : bias_in;
    int b  = blockIdx.z;
    int t0 = blockIdx.y * 128;
    int n0 = blockIdx.x * 128;
    int tid = threadIdx.x;
    int f_l = tid >> 4, v = tid & 15;
    int ty  = tid >> 4, tx = tid & 15;

    unsigned long long acc[4][8];
#pragma unroll
    for (int i = 0; i < 4; i++)
#pragma unroll
        for (int j = 0; j < 8; j++) acc[i][j] = 0ull;

    for (int kbase = 0; kbase < K; kbase += 16) {
        int f = kbase + f_l;
        const float* rowp;
        if (srcMode == 0) {
            rowp = Ain + (size_t)2 * IN_ * T_ + (size_t)b * 3 * IN_ * T_ + (size_t)f * T_;
        } else {
            rowp = (f < 64) ? (g_xeff + (size_t)b * IN_ * T_ + (size_t)f * T_)
                            : (Ain + (size_t)IN_ * T_ + (size_t)b * 3 * IN_ * T_ + (size_t)(f - 64) * T_);
        }
#pragma unroll
        for (int h = 0; h < 2; ++h) {
            int tg = t0 + (v + 16 * h) * 4;
            float4 av = make_float4(0.f, 0.f, 0.f, 0.f);
            if (tg < T_) av = *(const float4*)(rowp + tg);
            *(float4*)&As[f_l * 132 + (v + 16 * h) * 4] = av;
        }
#pragma unroll
        for (int it = 0; it < 2; ++it) {
            int lin = tid + it * 256;
            int kq = lin >> 5, vq = lin & 31;
            int ng = n0 + vq * 4;
            float4 wv = make_float4(0.f, 0.f, 0.f, 0.f);
            if (ng < Ncols)
                wv = *(const float4*)(Wp + (size_t)(kbase + kq) * ldw + ng);
            *(float4*)&Bs[kq * 128 + vq * 4] = wv;
        }
        __syncthreads();
#pragma unroll
        for (int kk = 0; kk < 16; ++kk) {
            ulonglong2 a0 = *(const ulonglong2*)&As[kk * 132 + ty * 8];
            ulonglong2 a1 = *(const ulonglong2*)&As[kk * 132 + ty * 8 + 4];
            float4 bq0 = *(const float4*)&Bs[kk * 128 + tx * 8];
            float4 bq1 = *(const float4*)&Bs[kk * 128 + tx * 8 + 4];
            unsigned long long ap[4] = {a0.x, a0.y, a1.x, a1.y};
            unsigned long long bp8[8] = {pack2(bq0.x), pack2(bq0.y), pack2(bq0.z), pack2(bq0.w),
                                         pack2(bq1.x), pack2(bq1.y), pack2(bq1.z), pack2(bq1.w)};
#pragma unroll
            for (int i = 0; i < 4; i++)
#pragma unroll
                for (int j = 0; j < 8; j++) acc[i][j] = ffma2(ap[i], bp8[j], acc[i][j]);
        }
        __syncthreads();
    }
    if (n0 + tx * 8 >= Ncols) return;
    float bl[8];
#pragma unroll
    for (int j = 0; j < 8; j++) bl[j] = bp[n0 + tx * 8 + j];
#pragma unroll
    for (int ip = 0; ip < 4; ip++) {
        float va[2][8];
#pragma unroll
        for (int j = 0; j < 8; j++) {
            float2 c = up2(acc[ip][j]);
            va[0][j] = c.x; va[1][j] = c.y;
        }
#pragma unroll
        for (int s = 0; s < 2; ++s) {
            int tg = t0 + ty * 8 + ip * 2 + s;
            if (tg >= T_) continue;
            float vv[8];
#pragma unroll
            for (int j = 0; j < 8; j++) {
                float x = va[s][j] + bl[j];
                if (actMode == 1) x = __expf(-fmaxf(x, 0.0f));
                vv[j] = x;
            }
            if (outMode == 0) {
                float* dst = g_act + ((size_t)b * T_ + tg) * 512 + outOff + n0 + tx * 8;
                *(float4*)dst       = make_float4(vv[0], vv[1], vv[2], vv[3]);
                *(float4*)(dst + 4) = make_float4(vv[4], vv[5], vv[6], vv[7]);
            } else {
#pragma unroll
                for (int j = 0; j < 8; j++)
                    g_gxT[((size_t)b * 64 + n0 + tx * 8 + j) * T_ + tg] = vv[j];
            }
        }
    }
}

// ---------------- two-pass LOCF scan ---------------------------------------
__global__ void scanA_kernel(const float* __restrict__ input) {
    int tid = blockIdx.x * blockDim.x + threadIdx.x;
    int c = tid % CH_;
    int bi = tid / CH_;
    int b = bi >> 6, i = bi & 63;
    const float4* Xp = (const float4*)(input + ((size_t)(b * 3 + 0) * IN_ + i) * T_ + c * CL_);
    const float4* Mp = (const float4*)(input + ((size_t)(b * 3 + 1) * IN_ + i) * T_ + c * CL_);
    float last = 0.f, has = 0.f;
#pragma unroll 5
    for (int v = 0; v < CL_ / 4; ++v) {
        float4 x4 = Xp[v], m4 = Mp[v];
        if (m4.x > 0.f) { last = x4.x; has = 1.f; }
        if (m4.y > 0.f) { last = x4.y; has = 1.f; }
        if (m4.z > 0.f) { last = x4.z; has = 1.f; }
        if (m4.w > 0.f) { last = x4.w; has = 1.f; }
    }
    g_lastx[tid] = last;
    g_hasx[tid] = has;
}

__global__ void scanB_kernel(const float* __restrict__ input, const float* __restrict__ x_mean) {
    int tid = blockIdx.x * blockDim.x + threadIdx.x;
    int c = tid % CH_;
    int bi = tid / CH_;
    int b = bi >> 6, i = bi & 63;
    float xl = 0.f;
    for (int cc = c - 1; cc >= 0; --cc) {
        if (g_hasx[bi * CH_ + cc] > 0.f) { xl = g_lastx[bi * CH_ + cc]; break; }
    }
    const float4* Xp = (const float4*)(input + ((size_t)(b * 3 + 0) * IN_ + i) * T_ + c * CL_);
    const float4* Mp = (const float4*)(input + ((size_t)(b * 3 + 1) * IN_ + i) * T_ + c * CL_);
    const float4* Gp = (const float4*)(g_gxT + ((size_t)b * IN_ + i) * T_ + c * CL_);
    float4*       Op = (float4*)(g_xeff + ((size_t)b * IN_ + i) * T_ + c * CL_);
    float xm = x_mean[i];
#pragma unroll 5
    for (int v = 0; v < CL_ / 4; ++v) {
        float4 x4 = Xp[v], m4 = Mp[v], g4 = Gp[v];
        float4 o;
        if (m4.x > 0.f) { xl = x4.x; o.x = x4.x; } else { o.x = g4.x * xl + (1.f - g4.x) * xm; }
        if (m4.y > 0.f) { xl = x4.y; o.y = x4.y; } else { o.y = g4.y * xl + (1.f - g4.y) * xm; }
        if (m4.z > 0.f) { xl = x4.z; o.z = x4.z; } else { o.z = g4.z * xl + (1.f - g4.z) * xm; }
        if (m4.w > 0.f) { xl = x4.w; o.w = x4.w; } else { o.w = g4.w * xl + (1.f - g4.w) * xm; }
        Op[v] = o;
    }
}

// ---------------- persistent recurrence, register-resident weights ---------
// 512 threads = col j (128) x part p (4). Each thread holds 32 k-slice of
// Whz/Whr/Whh for its column as 16 f32x2 k-pairs per matrix (96 regs).
// 2 batch rows per CTA, 128 CTAs. Reduction over parts via shfl.bfly.
// Part roles: p0 -> z (act A_z), p1 -> r (A_r), p2 -> h owner (gamma_h),
//             p3 -> h_tilde (A_h).
__global__ __launch_bounds__(512)
void recur_kernel(const float* __restrict__ Whz, const float* __restrict__ Whr,
                  const float* __restrict__ Whh, float* __restrict__ out) {
    __shared__ __align__(16) float hq0[128];
    __shared__ __align__(16) float hq1[128];
    __shared__ __align__(16) float hp0[128];
    __shared__ __align__(16) float hp1[128];

    int tid = threadIdx.x;
    int j = tid >> 2;       // output column 0..127
    int p = tid & 3;        // k-part 0..3
    int kb = p * 32;
    int b0 = blockIdx.x * 2;

    // load register weights: column j, k in [kb, kb+32), packed in k-pairs
    unsigned long long wz[16], wr[16], wh[16];
    {
        const float* Wzp = Whz + j;
        const float* Wrp = Whr + j;
        const float* Whp = Whh + j;
#pragma unroll
        for (int kk = 0; kk < 16; ++kk) {
            int k0 = (kb + 2 * kk) * 128;
            wz[kk] = packf2(Wzp[k0], Wzp[k0 + 128]);
            wr[kk] = packf2(Wrp[k0], Wrp[k0 + 128]);
            wh[kk] = packf2(Whp[k0], Whp[k0 + 128]);
        }
    }

    float* hs = out + (size_t)B_ * T_ * OUT_;
    float* hs0 = hs + ((size_t)b0 * T_) * 128 + j;
    float* hs1 = hs + ((size_t)(b0 + 1) * T_) * 128 + j;

    // per-part activation stream: p0->A_z(128), p1->A_r(256), p2->gamma_h(0), p3->A_h(384)
    int typeoff = (p == 0) ? 128 : (p == 1) ? 256 : (p == 2) ? 0 : 384;
    const float* ap0 = g_act + (size_t)b0 * T_ * 512 + typeoff + j;
    const float* ap1 = ap0 + (size_t)T_ * 512;

    float act0 = ap0[0];
    float act1 = ap1[0];

    float h0 = 0.f, h1 = 0.f;        // live in p2 only
    float hh0 = 0.f, hh1 = 0.f;

    for (int t = 0; t < T_; ++t) {
        // stage 1: p2 computes hh = gamma_h * h, publishes to smem
        if (p == 2) {
            hh0 = act0 * h0;
            hh1 = act1 * h1;
            hq0[j] = hh0;
            hq1[j] = hh1;
        }
        __syncthreads();

        // loop1: z and r partial GEMVs over own k-range (f32x2 k-pairs)
        unsigned long long za0 = 0ull, za1 = 0ull, ra0 = 0ull, ra1 = 0ull;
#pragma unroll
        for (int q = 0; q < 8; ++q) {
            ulonglong2 ha = *(const ulonglong2*)(hq0 + kb + q * 4);
            ulonglong2 hb = *(const ulonglong2*)(hq1 + kb + q * 4);
            za0 = ffma2(wz[2 * q], ha.x, za0);
            za0 = ffma2(wz[2 * q + 1], ha.y, za0);
            za1 = ffma2(wz[2 * q], hb.x, za1);
            za1 = ffma2(wz[2 * q + 1], hb.y, za1);
            ra0 = ffma2(wr[2 * q], ha.x, ra0);
            ra0 = ffma2(wr[2 * q + 1], ha.y, ra0);
            ra1 = ffma2(wr[2 * q], hb.x, ra1);
            ra1 = ffma2(wr[2 * q + 1], hb.y, ra1);
        }
        float sz0 = hsum2(za0), sz1 = hsum2(za1);
        float sr0 = hsum2(ra0), sr1 = hsum2(ra1);
        sz0 += __shfl_xor_sync(0xFFFFFFFFu, sz0, 1);
        sz0 += __shfl_xor_sync(0xFFFFFFFFu, sz0, 2);
        sz1 += __shfl_xor_sync(0xFFFFFFFFu, sz1, 1);
        sz1 += __shfl_xor_sync(0xFFFFFFFFu, sz1, 2);
        sr0 += __shfl_xor_sync(0xFFFFFFFFu, sr0, 1);
        sr0 += __shfl_xor_sync(0xFFFFFFFFu, sr0, 2);
        sr1 += __shfl_xor_sync(0xFFFFFFFFu, sr1, 1);
        sr1 += __shfl_xor_sync(0xFFFFFFFFu, sr1, 2);

        float z0 = 0.f, z1 = 0.f, r0 = 0.f, r1 = 0.f;
        if (p == 0) { z0 = sigf(sz0 + act0); z1 = sigf(sz1 + act1); }
        if (p == 1) { r0 = sigf(sr0 + act0); r1 = sigf(sr1 + act1); }

        // p1 needs hh (owned by p2): lane xor 3 maps p1<->p2
        float hh0b = __shfl_xor_sync(0xFFFFFFFFu, hh0, 3);
        float hh1b = __shfl_xor_sync(0xFFFFFFFFu, hh1, 3);
        if (p == 1) {
            hp0[j] = r0 * hh0b;
            hp1[j] = r1 * hh1b;
        }
        __syncthreads();

        // loop2: h_tilde partial GEMV
        unsigned long long ta0 = 0ull, ta1 = 0ull;
#pragma unroll
        for (int q = 0; q < 8; ++q) {
            ulonglong2 ha = *(const ulonglong2*)(hp0 + kb + q * 4);
            ulonglong2 hb = *(const ulonglong2*)(hp1 + kb + q * 4);
            ta0 = ffma2(wh[2 * q], ha.x, ta0);
            ta0 = ffma2(wh[2 * q + 1], ha.y, ta0);
            ta1 = ffma2(wh[2 * q], hb.x, ta1);
            ta1 = ffma2(wh[2 * q + 1], hb.y, ta1);
        }
        float st0 = hsum2(ta0), st1 = hsum2(ta1);
        st0 += __shfl_xor_sync(0xFFFFFFFFu, st0, 1);
        st0 += __shfl_xor_sync(0xFFFFFFFFu, st0, 2);
        st1 += __shfl_xor_sync(0xFFFFFFFFu, st1, 1);
        st1 += __shfl_xor_sync(0xFFFFFFFFu, st1, 2);

        float ht0 = 0.f, ht1 = 0.f;
        if (p == 3) { ht0 = tanhfast(st0 + act0); ht1 = tanhfast(st1 + act1); }

        // p2 needs z (p0: xor 2) and ht (p3: xor 1)
        float z0b = __shfl_xor_sync(0xFFFFFFFFu, z0, 2);
        float z1b = __shfl_xor_sync(0xFFFFFFFFu, z1, 2);
        float ht0b = __shfl_xor_sync(0xFFFFFFFFu, ht0, 1);
        float ht1b = __shfl_xor_sync(0xFFFFFFFFu, ht1, 1);

        if (p == 2) {
            h0 = hh0 + z0b * (ht0b - hh0);
            h1 = hh1 + z1b * (ht1b - hh1);
            hs0[(size_t)t * 128] = h0;
            hs1[(size_t)t * 128] = h1;
        }

        // prefetch next activations (clamped)
        int tt = (t + 1 < T_) ? (t + 1) : (T_ - 1);
        act0 = ap0[(size_t)tt * 512];
        act1 = ap1[(size_t)tt * 512];
    }
}

// ---------------- y = sigmoid(hs @ W_hy + b_hy) (f32x2, reg-packed B) -------
__global__ __launch_bounds__(256)
void gemmY_kernel(const float* __restrict__ Why, const float* __restrict__ bhy,
                  float* __restrict__ out) {
    __shared__ __align__(16) float As[16 * 132];
    __shared__ __align__(16) float Bs[16 * 64];
    const float* A = out + (size_t)B_ * T_ * OUT_;
    size_t r0 = (size_t)blockIdx.x * 128;
    int tid = threadIdx.x;
    int ty = tid >> 4, tx = tid & 15;

    unsigned long long acc[4][4];
#pragma unroll
    for (int i = 0; i < 4; i++)
#pragma unroll
        for (int j = 0; j < 4; j++) acc[i][j] = 0ull;

    for (int kbase = 0; kbase < 128; kbase += 16) {
        {
            int row = tid >> 2, c = tid & 3;
#pragma unroll
            for (int rr = 0; rr < 2; ++rr) {
                int r = row + rr * 64;
                float4 av = *(const float4*)(A + (r0 + r) * 128 + kbase + c * 4);
                As[(c * 4 + 0) * 132 + r] = av.x;
                As[(c * 4 + 1) * 132 + r] = av.y;
                As[(c * 4 + 2) * 132 + r] = av.z;
                As[(c * 4 + 3) * 132 + r] = av.w;
            }
        }
        {
            int f_l = tid >> 4, v = tid & 15;
            *(float4*)&Bs[f_l * 64 + v * 4] =
                *(const float4*)(Why + (size_t)(kbase + f_l) * 64 + v * 4);
        }
        __syncthreads();
#pragma unroll
        for (int kk = 0; kk < 16; ++kk) {
            ulonglong2 a0 = *(const ulonglong2*)&As[kk * 132 + ty * 8];
            ulonglong2 a1 = *(const ulonglong2*)&As[kk * 132 + ty * 8 + 4];
            float4 bq = *(const float4*)&Bs[kk * 64 + tx * 4];
            unsigned long long ap[4] = {a0.x, a0.y, a1.x, a1.y};
            unsigned long long bp4[4] = {pack2(bq.x), pack2(bq.y), pack2(bq.z), pack2(bq.w)};
#pragma unroll
            for (int i = 0; i < 4; i++)
#pragma unroll
                for (int j = 0; j < 4; j++) acc[i][j] = ffma2(ap[i], bp4[j], acc[i][j]);
        }
        __syncthreads();
    }
    float bl[4];
#pragma unroll
    for (int j = 0; j < 4; j++) bl[j] = bhy[tx * 4 + j];
#pragma unroll
    for (int ip = 0; ip < 4; ip++) {
        float2 c0 = up2(acc[ip][0]), c1 = up2(acc[ip][1]);
        float2 c2 = up2(acc[ip][2]), c3 = up2(acc[ip][3]);
        float va[2][4] = {{c0.x, c1.x, c2.x, c3.x}, {c0.y, c1.y, c2.y, c3.y}};
#pragma unroll
        for (int s = 0; s < 2; ++s) {
            size_t rg = r0 + ty * 8 + ip * 2 + s;
            float4 vo;
            vo.x = sigf(va[s][0] + bl[0]);
            vo.y = sigf(va[s][1] + bl[1]);
            vo.z = sigf(va[s][2] + bl[2]);
            vo.w = sigf(va[s][3] + bl[3]);
            *(float4*)(out + rg * 64 + tx * 4) = vo;
        }
    }
}

// ---------------- launch ----------------------------------------------------
extern "C" void kernel_launch(void* const* d_in, const int* in_sizes, int n_in,
                              void* d_out, int out_size) {
    const float* input  = (const float*)d_in[0];
    const float* x_mean = (const float*)d_in[1];
    const float* W_dg_x = (const float*)d_in[2];
    const float* b_dg_x = (const float*)d_in[3];
    const float* W_dg_h = (const float*)d_in[4];
    const float* b_dg_h = (const float*)d_in[5];
    const float* W_xz   = (const float*)d_in[6];
    const float* W_hz   = (const float*)d_in[7];
    const float* W_mz   = (const float*)d_in[8];
    const float* b_mz   = (const float*)d_in[9];
    const float* W_xr   = (const float*)d_in[10];
    const float* W_hr   = (const float*)d_in[11];
    const float* W_mr   = (const float*)d_in[12];
    const float* W_xh   = (const float*)d_in[13];
    const float* W_hh   = (const float*)d_in[14];
    const float* W_mh   = (const float*)d_in[15];
    const float* b_mh   = (const float*)d_in[16];
    const float* W_hy   = (const float*)d_in[17];
    const float* b_hy   = (const float*)d_in[18];
    float* out = (float*)d_out;

    pack_kernel<<<1, 256>>>(W_xz, W_mz, b_mz, W_xr, W_mr, W_xh, W_mh, b_mh);

    // chunk summaries for LOCF (depends only on input)
    scanA_kernel<<<(B_ * IN_ * CH_) / 256, 256>>>(input);

    // gamma_x: K=64, N=64 -> g_gxT (b,n,t)
    gemmT_kernel<<<dim3(1, 8, B_), 256>>>(input, W_dg_x, 64, 64, b_dg_x,
                                          64, /*act*/1, /*out*/1, 0, /*src*/0);
    // gamma_h: K=64, N=128 -> g_act[0:128)
    gemmT_kernel<<<dim3(1, 8, B_), 256>>>(input, W_dg_h, 128, 128, b_dg_h,
                                          64, 1, 0, 0, 0);
    // LOCF apply -> g_xeff
    scanB_kernel<<<(B_ * IN_ * CH_) / 256, 256>>>(input, x_mean);
    // A_zrh: K=128, N=384 -> g_act[128:512)
    gemmT_kernel<<<dim3(3, 8, B_), 256>>>(input, nullptr, 384, 384, nullptr,
                                          128, 0, 0, 128, 1);
    // recurrence -> hs region of d_out
    recur_kernel<<<128, 512>>>(W_hz, W_hr, W_hh, out);
    // y -> ys region of d_out
    gemmY_kernel<<<(B_ * T_) / 128, 256>>>(W_hy, b_hy, out);
}

// round 6
// speedup vs baseline: 2.2711x; 2.2711x over previous
#include <cuda_runtime.h>
#include <cuda_bf16.h>
#include <math.h>

#define B_   256
#define IN_  64
#define HID_ 128
#define OUT_ 64
#define T_   1000
#define CH_  10
#define CL_  100

// ---------------- device scratch (static, allocation-free) ----------------
__device__ float g_xeff[(size_t)B_ * IN_ * T_];   // (b, i, t) effective x
__device__ float g_gxT [(size_t)B_ * IN_ * T_];   // (b, n, t) gamma_x
// per (b,t): [0:128)=gamma_h  [128:256)=A_z  [256:384)=A_r  [384:512)=A_h
__device__ float g_act [(size_t)B_ * T_ * 512];
__device__ float g_wzrh[128 * 384];               // packed [x;m] -> [z|r|h]
__device__ float g_bzrh[384];
__device__ float g_wzr [128 * 64 * 4];            // [j][q] = {wz_2q, wz_2q+1, wr_2q, wr_2q+1}
__device__ float g_whT [128 * 128];               // [j][k] = Whh[k][j]
__device__ float g_lastx[B_ * IN_ * CH_];
__device__ float g_hasx [B_ * IN_ * CH_];

__device__ __forceinline__ float sigf(float x) { return 1.0f / (1.0f + __expf(-x)); }
__device__ __forceinline__ float tanhfast(float x) {
    float e = __expf(-2.0f * fabsf(x));
    float r = (1.0f - e) / (1.0f + e);
    return copysignf(r, x);
}
// packed f32x2 FMA (sm_10x)
__device__ __forceinline__ unsigned long long ffma2(unsigned long long a,
                                                    unsigned long long b,
                                                    unsigned long long c) {
    unsigned long long d;
    asm("fma.rn.f32x2 %0, %1, %2, %3;" : "=l"(d) : "l"(a), "l"(b), "l"(c));
    return d;
}
__device__ __forceinline__ unsigned long long pack2(float w) {
    unsigned long long d;
    asm("mov.b64 %0, {%1, %1};" : "=l"(d) : "f"(w));
    return d;
}
__device__ __forceinline__ float2 up2(unsigned long long u) {
    return make_float2(__uint_as_float((unsigned)u),
                       __uint_as_float((unsigned)(u >> 32)));
}
__device__ __forceinline__ float hsum2(unsigned long long u) {
    float2 c = up2(u);
    return c.x + c.y;
}

// ---------------- pack weights ---------------------------------------------
__global__ void pack_kernel(const float* __restrict__ Wxz, const float* __restrict__ Wmz,
                            const float* __restrict__ bmz,
                            const float* __restrict__ Wxr, const float* __restrict__ Wmr,
                            const float* __restrict__ Wxh, const float* __restrict__ Wmh,
                            const float* __restrict__ bmh,
                            const float* __restrict__ Whz, const float* __restrict__ Whr,
                            const float* __restrict__ Whh) {
    int tid0 = blockIdx.x * blockDim.x + threadIdx.x;
    for (int idx = tid0; idx < 128 * 384; idx += gridDim.x * blockDim.x) {
        int k = idx / 384, n = idx % 384;
        int mat = n >> 7, j = n & 127;
        const float* Wx = (mat == 0) ? Wxz : ((mat == 1) ? Wxr : Wxh);
        const float* Wm = (mat == 0) ? Wmz : ((mat == 1) ? Wmr : Wmh);
        g_wzrh[idx] = (k < 64) ? Wx[k * 128 + j] : Wm[(k - 64) * 128 + j];
    }
    for (int n = tid0; n < 384; n += gridDim.x * blockDim.x) {
        int mat = n >> 7, j = n & 127;
        g_bzrh[n] = (mat == 0) ? bmz[j] : ((mat == 2) ? bmh[j] : 0.0f);
    }
    // zr interleaved pairs: [j][q] float4
    for (int idx = tid0; idx < 128 * 64; idx += gridDim.x * blockDim.x) {
        int j = idx >> 6, q = idx & 63;
        float4 v;
        v.x = Whz[(2 * q) * 128 + j];
        v.y = Whz[(2 * q + 1) * 128 + j];
        v.z = Whr[(2 * q) * 128 + j];
        v.w = Whr[(2 * q + 1) * 128 + j];
        *(float4*)&g_wzr[idx * 4] = v;
    }
    // h transposed
    for (int idx = tid0; idx < 128 * 128; idx += gridDim.x * blockDim.x) {
        int j = idx >> 7, k = idx & 127;
        g_whT[idx] = Whh[k * 128 + j];
    }
}

// ---------------- GEMM over feature-major A (f32x2, 128x128 tile) ----------
__global__ __launch_bounds__(256, 2)
void gemmT_kernel(const float* __restrict__ Ain,
                  const float* __restrict__ W_in, int ldw, int Ncols,
                  const float* __restrict__ bias_in,
                  int K, int actMode, int outMode, int outOff, int srcMode) {
    __shared__ __align__(16) float As[16 * 132];
    __shared__ __align__(16) float Bs[16 * 128];
    const float* Wp = srcMode ? g_wzrh : W_in;
    const float* bp = srcMode ? g_bzrh : bias_in;
    int b  = blockIdx.z;
    int t0 = blockIdx.y * 128;
    int n0 = blockIdx.x * 128;
    int tid = threadIdx.x;
    int f_l = tid >> 4, v = tid & 15;
    int ty  = tid >> 4, tx = tid & 15;

    unsigned long long acc[4][8];
#pragma unroll
    for (int i = 0; i < 4; i++)
#pragma unroll
        for (int j = 0; j < 8; j++) acc[i][j] = 0ull;

    for (int kbase = 0; kbase < K; kbase += 16) {
        int f = kbase + f_l;
        const float* rowp;
        if (srcMode == 0) {
            rowp = Ain + (size_t)2 * IN_ * T_ + (size_t)b * 3 * IN_ * T_ + (size_t)f * T_;
        } else {
            rowp = (f < 64) ? (g_xeff + (size_t)b * IN_ * T_ + (size_t)f * T_)
                            : (Ain + (size_t)IN_ * T_ + (size_t)b * 3 * IN_ * T_ + (size_t)(f - 64) * T_);
        }
#pragma unroll
        for (int h = 0; h < 2; ++h) {
            int tg = t0 + (v + 16 * h) * 4;
            float4 av = make_float4(0.f, 0.f, 0.f, 0.f);
            if (tg < T_) av = *(const float4*)(rowp + tg);
            *(float4*)&As[f_l * 132 + (v + 16 * h) * 4] = av;
        }
#pragma unroll
        for (int it = 0; it < 2; ++it) {
            int lin = tid + it * 256;
            int kq = lin >> 5, vq = lin & 31;
            int ng = n0 + vq * 4;
            float4 wv = make_float4(0.f, 0.f, 0.f, 0.f);
            if (ng < Ncols)
                wv = *(const float4*)(Wp + (size_t)(kbase + kq) * ldw + ng);
            *(float4*)&Bs[kq * 128 + vq * 4] = wv;
        }
        __syncthreads();
#pragma unroll
        for (int kk = 0; kk < 16; ++kk) {
            ulonglong2 a0 = *(const ulonglong2*)&As[kk * 132 + ty * 8];
            ulonglong2 a1 = *(const ulonglong2*)&As[kk * 132 + ty * 8 + 4];
            float4 bq0 = *(const float4*)&Bs[kk * 128 + tx * 8];
            float4 bq1 = *(const float4*)&Bs[kk * 128 + tx * 8 + 4];
            unsigned long long ap[4] = {a0.x, a0.y, a1.x, a1.y};
            unsigned long long bp8[8] = {pack2(bq0.x), pack2(bq0.y), pack2(bq0.z), pack2(bq0.w),
                                         pack2(bq1.x), pack2(bq1.y), pack2(bq1.z), pack2(bq1.w)};
#pragma unroll
            for (int i = 0; i < 4; i++)
#pragma unroll
                for (int j = 0; j < 8; j++) acc[i][j] = ffma2(ap[i], bp8[j], acc[i][j]);
        }
        __syncthreads();
    }
    if (n0 + tx * 8 >= Ncols) return;
    float bl[8];
#pragma unroll
    for (int j = 0; j < 8; j++) bl[j] = bp[n0 + tx * 8 + j];
#pragma unroll
    for (int ip = 0; ip < 4; ip++) {
        float va[2][8];
#pragma unroll
        for (int j = 0; j < 8; j++) {
            float2 c = up2(acc[ip][j]);
            va[0][j] = c.x; va[1][j] = c.y;
        }
#pragma unroll
        for (int s = 0; s < 2; ++s) {
            int tg = t0 + ty * 8 + ip * 2 + s;
            if (tg >= T_) continue;
            float vv[8];
#pragma unroll
            for (int j = 0; j < 8; j++) {
                float x = va[s][j] + bl[j];
                if (actMode == 1) x = __expf(-fmaxf(x, 0.0f));
                vv[j] = x;
            }
            if (outMode == 0) {
                float* dst = g_act + ((size_t)b * T_ + tg) * 512 + outOff + n0 + tx * 8;
                *(float4*)dst       = make_float4(vv[0], vv[1], vv[2], vv[3]);
                *(float4*)(dst + 4) = make_float4(vv[4], vv[5], vv[6], vv[7]);
            } else {
#pragma unroll
                for (int j = 0; j < 8; j++)
                    g_gxT[((size_t)b * 64 + n0 + tx * 8 + j) * T_ + tg] = vv[j];
            }
        }
    }
}

// ---------------- two-pass LOCF scan ---------------------------------------
__global__ void scanA_kernel(const float* __restrict__ input) {
    int tid = blockIdx.x * blockDim.x + threadIdx.x;
    int c = tid % CH_;
    int bi = tid / CH_;
    int b = bi >> 6, i = bi & 63;
    const float4* Xp = (const float4*)(input + ((size_t)(b * 3 + 0) * IN_ + i) * T_ + c * CL_);
    const float4* Mp = (const float4*)(input + ((size_t)(b * 3 + 1) * IN_ + i) * T_ + c * CL_);
    float last = 0.f, has = 0.f;
#pragma unroll 5
    for (int v = 0; v < CL_ / 4; ++v) {
        float4 x4 = Xp[v], m4 = Mp[v];
        if (m4.x > 0.f) { last = x4.x; has = 1.f; }
        if (m4.y > 0.f) { last = x4.y; has = 1.f; }
        if (m4.z > 0.f) { last = x4.z; has = 1.f; }
        if (m4.w > 0.f) { last = x4.w; has = 1.f; }
    }
    g_lastx[tid] = last;
    g_hasx[tid] = has;
}

__global__ void scanB_kernel(const float* __restrict__ input, const float* __restrict__ x_mean) {
    int tid = blockIdx.x * blockDim.x + threadIdx.x;
    int c = tid % CH_;
    int bi = tid / CH_;
    int b = bi >> 6, i = bi & 63;
    float xl = 0.f;
    for (int cc = c - 1; cc >= 0; --cc) {
        if (g_hasx[bi * CH_ + cc] > 0.f) { xl = g_lastx[bi * CH_ + cc]; break; }
    }
    const float4* Xp = (const float4*)(input + ((size_t)(b * 3 + 0) * IN_ + i) * T_ + c * CL_);
    const float4* Mp = (const float4*)(input + ((size_t)(b * 3 + 1) * IN_ + i) * T_ + c * CL_);
    const float4* Gp = (const float4*)(g_gxT + ((size_t)b * IN_ + i) * T_ + c * CL_);
    float4*       Op = (float4*)(g_xeff + ((size_t)b * IN_ + i) * T_ + c * CL_);
    float xm = x_mean[i];
#pragma unroll 5
    for (int v = 0; v < CL_ / 4; ++v) {
        float4 x4 = Xp[v], m4 = Mp[v], g4 = Gp[v];
        float4 o;
        if (m4.x > 0.f) { xl = x4.x; o.x = x4.x; } else { o.x = g4.x * xl + (1.f - g4.x) * xm; }
        if (m4.y > 0.f) { xl = x4.y; o.y = x4.y; } else { o.y = g4.y * xl + (1.f - g4.y) * xm; }
        if (m4.z > 0.f) { xl = x4.z; o.z = x4.z; } else { o.z = g4.z * xl + (1.f - g4.z) * xm; }
        if (m4.w > 0.f) { xl = x4.w; o.w = x4.w; } else { o.w = g4.w * xl + (1.f - g4.w) * xm; }
        Op[v] = o;
    }
}

// ---------------- persistent recurrence: 2 rows/CTA, zero-mov f32x2 --------
// 128 threads; thread j owns column j for both rows. Weights in smem,
// pre-paired: Wzr[j][q] = {wz_2q, wz_2q+1, wr_2q, wr_2q+1} (stride 65 float4),
// Whs[j][k] transposed (stride 132 floats). One LDS.128 = two f32x2 operands.
#define WZR_STRIDE 65
#define WH_STRIDE  132
__global__ __launch_bounds__(128, 1)
void recur_kernel(float* __restrict__ out) {
    extern __shared__ __align__(16) float sm[];
    float* Wzr = sm;                              // 128 * 65 * 4 floats
    float* Whs = Wzr + 128 * WZR_STRIDE * 4;      // 128 * 132 floats
    float* hq0 = Whs + 128 * WH_STRIDE;
    float* hq1 = hq0 + 128;
    float* hp0 = hq1 + 128;
    float* hp1 = hp0 + 128;

    int tid = threadIdx.x;
    int b0 = blockIdx.x * 2, b1 = b0 + 1;

    // load weights into padded smem
    for (int idx = tid; idx < 128 * 64; idx += 128) {
        int j = idx >> 6, q = idx & 63;
        *(float4*)&Wzr[(j * WZR_STRIDE + q) * 4] = *(const float4*)&g_wzr[idx * 4];
    }
    for (int idx = tid; idx < 128 * 128; idx += 128) {
        int j = idx >> 7, k = idx & 127;
        Whs[j * WH_STRIDE + k] = g_whT[idx];
    }
    __syncthreads();

    float* hs = out + (size_t)B_ * T_ * OUT_;

    const float* act0 = g_act + (size_t)b0 * T_ * 512 + tid;
    const float* act1 = g_act + (size_t)b1 * T_ * 512 + tid;

    float h0 = 0.f, h1 = 0.f;
    float gh0 = act0[0], az0 = act0[128], ar0 = act0[256], ah0 = act0[384];
    float gh1 = act1[0], az1 = act1[128], ar1 = act1[256], ah1 = act1[384];

    const ulonglong2* wzr2 = (const ulonglong2*)(Wzr + tid * WZR_STRIDE * 4);
    const float* whp = Whs + tid * WH_STRIDE;

    for (int t = 0; t < T_; ++t) {
        float hh0 = gh0 * h0;
        float hh1 = gh1 * h1;
        hq0[tid] = hh0;
        hq1[tid] = hh1;

        // prefetch next step activations
        float ngh0 = gh0, naz0 = az0, nar0 = ar0, nah0 = ah0;
        float ngh1 = gh1, naz1 = az1, nar1 = ar1, nah1 = ah1;
        if (t + 1 < T_) {
            const float* a0 = act0 + (size_t)(t + 1) * 512;
            const float* a1 = act1 + (size_t)(t + 1) * 512;
            ngh0 = a0[0]; naz0 = a0[128]; nar0 = a0[256]; nah0 = a0[384];
            ngh1 = a1[0]; naz1 = a1[128]; nar1 = a1[256]; nah1 = a1[384];
        }
        __syncthreads();

        // z/r GEMV: 8 independent f32x2 chains
        unsigned long long za0 = 0ull, za1 = 0ull, ra0 = 0ull, ra1 = 0ull;
        unsigned long long zb0 = 0ull, zb1 = 0ull, rb0 = 0ull, rb1 = 0ull;
#pragma unroll
        for (int q2 = 0; q2 < 32; ++q2) {
            ulonglong2 w0 = wzr2[2 * q2];
            ulonglong2 w1 = wzr2[2 * q2 + 1];
            ulonglong2 h0p = *(const ulonglong2*)(hq0 + q2 * 4);
            ulonglong2 h1p = *(const ulonglong2*)(hq1 + q2 * 4);
            za0 = ffma2(w0.x, h0p.x, za0); ra0 = ffma2(w0.y, h0p.x, ra0);
            za1 = ffma2(w0.x, h1p.x, za1); ra1 = ffma2(w0.y, h1p.x, ra1);
            zb0 = ffma2(w1.x, h0p.y, zb0); rb0 = ffma2(w1.y, h0p.y, rb0);
            zb1 = ffma2(w1.x, h1p.y, zb1); rb1 = ffma2(w1.y, h1p.y, rb1);
        }
        float z0 = sigf(hsum2(za0) + hsum2(zb0) + az0);
        float z1 = sigf(hsum2(za1) + hsum2(zb1) + az1);
        float r0 = sigf(hsum2(ra0) + hsum2(rb0) + ar0);
        float r1 = sigf(hsum2(ra1) + hsum2(rb1) + ar1);

        hp0[tid] = r0 * hh0;
        hp1[tid] = r1 * hh1;
        __syncthreads();

        // h_tilde GEMV: 4 chains
        unsigned long long ta0 = 0ull, tb0 = 0ull, ta1 = 0ull, tb1 = 0ull;
#pragma unroll
        for (int q4 = 0; q4 < 32; ++q4) {
            ulonglong2 wp = *(const ulonglong2*)(whp + q4 * 4);
            ulonglong2 p0 = *(const ulonglong2*)(hp0 + q4 * 4);
            ulonglong2 p1 = *(const ulonglong2*)(hp1 + q4 * 4);
            ta0 = ffma2(wp.x, p0.x, ta0); tb0 = ffma2(wp.y, p0.y, tb0);
            ta1 = ffma2(wp.x, p1.x, ta1); tb1 = ffma2(wp.y, p1.y, tb1);
        }
        float ht0 = tanhfast(hsum2(ta0) + hsum2(tb0) + ah0);
        float ht1 = tanhfast(hsum2(ta1) + hsum2(tb1) + ah1);

        h0 = hh0 + z0 * (ht0 - hh0);
        h1 = hh1 + z1 * (ht1 - hh1);

        hs[((size_t)b0 * T_ + t) * 128 + tid] = h0;
        hs[((size_t)b1 * T_ + t) * 128 + tid] = h1;

        gh0 = ngh0; az0 = naz0; ar0 = nar0; ah0 = nah0;
        gh1 = ngh1; az1 = naz1; ar1 = nar1; ah1 = nah1;
    }
}

// ---------------- y = sigmoid(hs @ W_hy + b_hy) (f32x2, reg-packed B) -------
__global__ __launch_bounds__(256)
void gemmY_kernel(const float* __restrict__ Why, const float* __restrict__ bhy,
                  float* __restrict__ out) {
    __shared__ __align__(16) float As[16 * 132];
    __shared__ __align__(16) float Bs[16 * 64];
    const float* A = out + (size_t)B_ * T_ * OUT_;
    size_t r0 = (size_t)blockIdx.x * 128;
    int tid = threadIdx.x;
    int ty = tid >> 4, tx = tid & 15;

    unsigned long long acc[4][4];
#pragma unroll
    for (int i = 0; i < 4; i++)
#pragma unroll
        for (int j = 0; j < 4; j++) acc[i][j] = 0ull;

    for (int kbase = 0; kbase < 128; kbase += 16) {
        {
            int row = tid >> 2, c = tid & 3;
#pragma unroll
            for (int rr = 0; rr < 2; ++rr) {
                int r = row + rr * 64;
                float4 av = *(const float4*)(A + (r0 + r) * 128 + kbase + c * 4);
                As[(c * 4 + 0) * 132 + r] = av.x;
                As[(c * 4 + 1) * 132 + r] = av.y;
                As[(c * 4 + 2) * 132 + r] = av.z;
                As[(c * 4 + 3) * 132 + r] = av.w;
            }
        }
        {
            int f_l = tid >> 4, v = tid & 15;
            *(float4*)&Bs[f_l * 64 + v * 4] =
                *(const float4*)(Why + (size_t)(kbase + f_l) * 64 + v * 4);
        }
        __syncthreads();
#pragma unroll
        for (int kk = 0; kk < 16; ++kk) {
            ulonglong2 a0 = *(const ulonglong2*)&As[kk * 132 + ty * 8];
            ulonglong2 a1 = *(const ulonglong2*)&As[kk * 132 + ty * 8 + 4];
            float4 bq = *(const float4*)&Bs[kk * 64 + tx * 4];
            unsigned long long ap[4] = {a0.x, a0.y, a1.x, a1.y};
            unsigned long long bp4[4] = {pack2(bq.x), pack2(bq.y), pack2(bq.z), pack2(bq.w)};
#pragma unroll
            for (int i = 0; i < 4; i++)
#pragma unroll
                for (int j = 0; j < 4; j++) acc[i][j] = ffma2(ap[i], bp4[j], acc[i][j]);
        }
        __syncthreads();
    }
    float bl[4];
#pragma unroll
    for (int j = 0; j < 4; j++) bl[j] = bhy[tx * 4 + j];
#pragma unroll
    for (int ip = 0; ip < 4; ip++) {
        float2 c0 = up2(acc[ip][0]), c1 = up2(acc[ip][1]);
        float2 c2 = up2(acc[ip][2]), c3 = up2(acc[ip][3]);
        float va[2][4] = {{c0.x, c1.x, c2.x, c3.x}, {c0.y, c1.y, c2.y, c3.y}};
#pragma unroll
        for (int s = 0; s < 2; ++s) {
            size_t rg = r0 + ty * 8 + ip * 2 + s;
            float4 vo;
            vo.x = sigf(va[s][0] + bl[0]);
            vo.y = sigf(va[s][1] + bl[1]);
            vo.z = sigf(va[s][2] + bl[2]);
            vo.w = sigf(va[s][3] + bl[3]);
            *(float4*)(out + rg * 64 + tx * 4) = vo;
        }
    }
}

// ---------------- launch ----------------------------------------------------
extern "C" void kernel_launch(void* const* d_in, const int* in_sizes, int n_in,
                              void* d_out, int out_size) {
    const float* input  = (const float*)d_in[0];
    const float* x_mean = (const float*)d_in[1];
    const float* W_dg_x = (const float*)d_in[2];
    const float* b_dg_x = (const float*)d_in[3];
    const float* W_dg_h = (const float*)d_in[4];
    const float* b_dg_h = (const float*)d_in[5];
    const float* W_xz   = (const float*)d_in[6];
    const float* W_hz   = (const float*)d_in[7];
    const float* W_mz   = (const float*)d_in[8];
    const float* b_mz   = (const float*)d_in[9];
    const float* W_xr   = (const float*)d_in[10];
    const float* W_hr   = (const float*)d_in[11];
    const float* W_mr   = (const float*)d_in[12];
    const float* W_xh   = (const float*)d_in[13];
    const float* W_hh   = (const float*)d_in[14];
    const float* W_mh   = (const float*)d_in[15];
    const float* b_mh   = (const float*)d_in[16];
    const float* W_hy   = (const float*)d_in[17];
    const float* b_hy   = (const float*)d_in[18];
    float* out = (float*)d_out;

    const int recur_smem = (128 * WZR_STRIDE * 4 + 128 * WH_STRIDE + 4 * 128) * 4;

    static bool attr_set = false;
    if (!attr_set) {
        cudaFuncSetAttribute(recur_kernel, cudaFuncAttributeMaxDynamicSharedMemorySize,
                             recur_smem);
        attr_set = true;
    }

    pack_kernel<<<32, 256>>>(W_xz, W_mz, b_mz, W_xr, W_mr, W_xh, W_mh, b_mh,
                             W_hz, W_hr, W_hh);

    // chunk summaries for LOCF (depends only on input)
    scanA_kernel<<<(B_ * IN_ * CH_) / 256, 256>>>(input);

    // gamma_x: K=64, N=64 -> g_gxT (b,n,t)
    gemmT_kernel<<<dim3(1, 8, B_), 256>>>(input, W_dg_x, 64, 64, b_dg_x,
                                          64, /*act*/1, /*out*/1, 0, /*src*/0);
    // gamma_h: K=64, N=128 -> g_act[0:128)
    gemmT_kernel<<<dim3(1, 8, B_), 256>>>(input, W_dg_h, 128, 128, b_dg_h,
                                          64, 1, 0, 0, 0);
    // LOCF apply -> g_xeff
    scanB_kernel<<<(B_ * IN_ * CH_) / 256, 256>>>(input, x_mean);
    // A_zrh: K=128, N=384 -> g_act[128:512)
    gemmT_kernel<<<dim3(3, 8, B_), 256>>>(input, nullptr, 384, 384, nullptr,
                                          128, 0, 0, 128, 1);
    // recurrence -> hs region of d_out
    recur_kernel<<<128, 128, recur_smem>>>(out);
    // y -> ys region of d_out
    gemmY_kernel<<<(B_ * T_) / 128, 256>>>(W_hy, b_hy, out);
}